// round 5
// baseline (speedup 1.0000x reference)
#include <cuda_runtime.h>

#define NPIX  65536   // 256*256
#define NT    512
#define KS    16      // NPIX/8/NT uint4 (8 x u16) groups per thread for Lloyd scan
#define KG    32      // NPIX/4/NT float4 groups per thread (loss indexing)

#define CH1   4096    // phase-1 chunk pixels (per channel)
#define NCH1  16      // 65536/4096
#define CH3   8192    // phase-3 chunk pixels
#define NCH3  8       // 65536/8192

// SMEM layout (bytes):
//   [0, 131072)          q16 image (u16 per pixel), aliased as u64/uint4
//   [131072, 229376)     stage: phase1 = 2 stages x 3 ch x 4096 f32 (48KB each)
//                               phase3 = 2 stages x 8192 f32 (32KB each)
//   [229376, ...)        Scratch (mbarriers + reductions)
#define Q_BYTES      131072
#define STAGE_OFF    131072
#define SMEM_TOTAL   (229376 + 1024)

__device__ double   g_partials[1024];
__device__ unsigned g_count = 0;

struct Scratch {
    unsigned long long fullA[2], emptyA[2], fullB[2], emptyB[2];
    unsigned nred[16];
    unsigned sred[16];
    float    fmin[16], fmax[16], facc[16];
    int      qt, done, flip;
    unsigned border[4];
};

__device__ __forceinline__ unsigned smem_u32(const void* p) {
    unsigned r;
    asm("{ .reg .u64 t; cvta.to.shared.u64 t, %1; cvt.u32.u64 %0, t; }"
        : "=r"(r) : "l"(p));
    return r;
}
__device__ __forceinline__ void mbar_init(unsigned mbar, unsigned count) {
    asm volatile("mbarrier.init.shared.b64 [%0], %1;" :: "r"(mbar), "r"(count) : "memory");
}
__device__ __forceinline__ void mbar_arrive(unsigned mbar) {
    asm volatile("mbarrier.arrive.shared.b64 _, [%0];" :: "r"(mbar) : "memory");
}
__device__ __forceinline__ void mbar_expect_tx(unsigned mbar, unsigned bytes) {
    asm volatile("mbarrier.arrive.expect_tx.shared.b64 _, [%0], %1;"
                 :: "r"(mbar), "r"(bytes) : "memory");
}
__device__ __forceinline__ void mbar_wait(unsigned mbar, unsigned parity) {
    asm volatile(
        "{\n\t.reg .pred P;\n\t"
        "WL_%=:\n\t"
        "mbarrier.try_wait.parity.acquire.cta.shared::cta.b64 P, [%0], %1, 0x989680;\n\t"
        "@P bra WD_%=;\n\t"
        "bra WL_%=;\n\t"
        "WD_%=:\n\t}"
        :: "r"(mbar), "r"(parity) : "memory");
}
__device__ __forceinline__ void bulk_g2s(unsigned dst_smem, const void* src, unsigned bytes,
                                         unsigned mbar) {
    asm volatile(
        "cp.async.bulk.shared::cluster.global.mbarrier::complete_tx::bytes [%0], [%1], %2, [%3];"
        :: "r"(dst_smem), "l"(src), "r"(bytes), "r"(mbar) : "memory");
}

extern "C" __global__ void __launch_bounds__(NT, 1)
mask_loss_main(const float* __restrict__ hr, const float* __restrict__ sr,
               float* __restrict__ out, int B)
{
    extern __shared__ unsigned char smem[];
    unsigned short*     qs   = (unsigned short*)smem;
    unsigned long long* q64  = (unsigned long long*)smem;
    uint4*              q128 = (uint4*)smem;
    float*              stg  = (float*)(smem + STAGE_OFF);
    Scratch* sc = (Scratch*)(smem + 229376);

    const int tid  = threadIdx.x;
    const int lane = tid & 31;
    const int warp = tid >> 5;
    const int b    = blockIdx.x;

    const unsigned stg_u32 = smem_u32(stg);
    unsigned fa[2], ea[2], fb[2], eb[2];
    fa[0] = smem_u32(&sc->fullA[0]);  fa[1] = smem_u32(&sc->fullA[1]);
    ea[0] = smem_u32(&sc->emptyA[0]); ea[1] = smem_u32(&sc->emptyA[1]);
    fb[0] = smem_u32(&sc->fullB[0]);  fb[1] = smem_u32(&sc->fullB[1]);
    eb[0] = smem_u32(&sc->emptyB[0]); eb[1] = smem_u32(&sc->emptyB[1]);

    if (tid == 0) {
        mbar_init(fa[0], 1);  mbar_init(fa[1], 1);
        mbar_init(ea[0], NT); mbar_init(ea[1], NT);
        mbar_init(fb[0], 1);  mbar_init(fb[1], 1);
        mbar_init(eb[0], NT); mbar_init(eb[1], NT);
    }
    __syncthreads();

    // ---------------- Phase 1: TMA-staged gray + quantize into SMEM ----------------
    const float* base = hr + (size_t)b * 3 * NPIX;
    const float inv3 = 1.0f / 3.0f;

    // prologue: issue chunks 0, 1
    if (tid == 0) {
        #pragma unroll
        for (int k = 0; k < 2; k++) {
            mbar_expect_tx(fa[k], 3 * CH1 * 4);
            #pragma unroll
            for (int ch = 0; ch < 3; ch++)
                bulk_g2s(stg_u32 + (unsigned)((k * 3 + ch) * CH1 * 4),
                         base + ch * NPIX + k * CH1, CH1 * 4, fa[k]);
        }
    }

    float gmin = 3.0e38f, gmax = -3.0e38f;
    unsigned long long sq = 0;

    for (int k = 0; k < NCH1; k++) {
        const int s = k & 1;
        const unsigned par = (unsigned)((k >> 1) & 1);
        mbar_wait(fa[s], par);

        const float* c0 = stg + (s * 3 + 0) * CH1;
        const float* c1 = stg + (s * 3 + 1) * CH1;
        const float* c2 = stg + (s * 3 + 2) * CH1;
        const int t4 = tid * 2;   // float4 index of first of 2 groups (8 px/thread)

        unsigned qv[8];
        #pragma unroll
        for (int g = 0; g < 2; g++) {
            float4 a = ((const float4*)c0)[t4 + g];
            float4 c = ((const float4*)c1)[t4 + g];
            float4 d = ((const float4*)c2)[t4 + g];
            float x0 = (a.x + c.x + d.x) * inv3;
            float x1 = (a.y + c.y + d.y) * inv3;
            float x2 = (a.z + c.z + d.z) * inv3;
            float x3 = (a.w + c.w + d.w) * inv3;
            gmin = fminf(gmin, fminf(fminf(x0, x1), fminf(x2, x3)));
            gmax = fmaxf(gmax, fmaxf(fmaxf(x0, x1), fmaxf(x2, x3)));
            qv[g*4+0] = (unsigned)fminf(x0 * 65536.0f, 65535.0f);
            qv[g*4+1] = (unsigned)fminf(x1 * 65536.0f, 65535.0f);
            qv[g*4+2] = (unsigned)fminf(x2 * 65536.0f, 65535.0f);
            qv[g*4+3] = (unsigned)fminf(x3 * 65536.0f, 65535.0f);
        }
        #pragma unroll
        for (int j = 0; j < 8; j++) sq += (unsigned long long)qv[j];

        uint4 pk;
        pk.x = qv[0] | (qv[1] << 16);
        pk.y = qv[2] | (qv[3] << 16);
        pk.z = qv[4] | (qv[5] << 16);
        pk.w = qv[6] | (qv[7] << 16);
        q128[k * (CH1/8) + tid] = pk;   // pixel block (k*4096 + tid*8)/8

        mbar_arrive(ea[s]);
        if (tid == 0 && k + 2 < NCH1) {
            mbar_wait(ea[s], par);
            mbar_expect_tx(fa[s], 3 * CH1 * 4);
            #pragma unroll
            for (int ch = 0; ch < 3; ch++)
                bulk_g2s(stg_u32 + (unsigned)((s * 3 + ch) * CH1 * 4),
                         base + ch * NPIX + (k + 2) * CH1, CH1 * 4, fa[s]);
        }
    }

    // reduce min/max/sum
    #pragma unroll
    for (int o = 16; o; o >>= 1) {
        gmin = fminf(gmin, __shfl_xor_sync(~0u, gmin, o));
        gmax = fmaxf(gmax, __shfl_xor_sync(~0u, gmax, o));
        sq  += __shfl_xor_sync(~0u, sq, o);
    }
    if (lane == 0) {
        sc->fmin[warp] = gmin; sc->fmax[warp] = gmax;
        sc->nred[warp] = (unsigned)(sq & 0xFFFFFFFFull);
        sc->sred[warp] = (unsigned)(sq >> 32);
    }
    __syncthreads();

    double Stot = 0.0;   // valid only in (warp 0, lane 0)
    if (warp == 0 && lane < 16) {
        float mn = sc->fmin[lane];
        float mx = sc->fmax[lane];
        unsigned long long s = ((unsigned long long)sc->sred[lane] << 32)
                             | (unsigned long long)sc->nred[lane];
        #pragma unroll
        for (int o = 8; o; o >>= 1) {
            mn = fminf(mn, __shfl_xor_sync(0xFFFFu, mn, o));
            mx = fmaxf(mx, __shfl_xor_sync(0xFFFFu, mx, o));
            s += __shfl_xor_sync(0xFFFFu, s, o);
        }
        if (lane == 0) {
            Stot = ((double)s + 32768.0) * (1.0 / 65536.0);
            float t = 0.5f * (mn + mx);                 // init c0=min, c1=max
            sc->qt   = (int)floorf(t * 65536.0f - 0.5f);
            sc->done = 0;
        }
    }
    __syncthreads();

    // prefetch sr chunks 0,1 — TMA overlaps the Lloyd loop (stage region is free now)
    const float* srb = sr + (size_t)b * NPIX;
    if (tid == 0) {
        #pragma unroll
        for (int k = 0; k < 2; k++) {
            mbar_expect_tx(fb[k], CH3 * 4);
            bulk_g2s(stg_u32 + (unsigned)(k * CH3 * 4), srb + k * CH3, CH3 * 4, fb[k]);
        }
    }

    // ---------------- Phase 2: Lloyd iterations (integer threshold map) ----------------
    int qt = sc->qt;
    int prev = -0x70000000;  // thread-0-only history (tau_{i-1})

    for (int it = 0; it < 20; it++) {
        unsigned n = 0, s = 0;
        #pragma unroll
        for (int k = 0; k < KS; k++) {
            uint4 v = q128[tid + k * NT];
            int a0 = (int)(v.x & 0xFFFFu), a1 = (int)(v.x >> 16);
            int a2 = (int)(v.y & 0xFFFFu), a3 = (int)(v.y >> 16);
            int a4 = (int)(v.z & 0xFFFFu), a5 = (int)(v.z >> 16);
            int a6 = (int)(v.w & 0xFFFFu), a7 = (int)(v.w >> 16);
            if (a0 > qt) { n++; s += (unsigned)a0; }
            if (a1 > qt) { n++; s += (unsigned)a1; }
            if (a2 > qt) { n++; s += (unsigned)a2; }
            if (a3 > qt) { n++; s += (unsigned)a3; }
            if (a4 > qt) { n++; s += (unsigned)a4; }
            if (a5 > qt) { n++; s += (unsigned)a5; }
            if (a6 > qt) { n++; s += (unsigned)a6; }
            if (a7 > qt) { n++; s += (unsigned)a7; }
        }
        #pragma unroll
        for (int o = 16; o; o >>= 1) {
            n += __shfl_xor_sync(~0u, n, o);
            s += __shfl_xor_sync(~0u, s, o);
        }
        if (lane == 0) { sc->nred[warp] = n; sc->sred[warp] = s; }
        __syncthreads();

        if (warp == 0 && lane < 16) {
            unsigned N1 = sc->nred[lane];
            unsigned long long S1 = (unsigned long long)sc->sred[lane];
            #pragma unroll
            for (int o = 8; o; o >>= 1) {
                N1 += __shfl_xor_sync(0xFFFFu, N1, o);
                S1 += __shfl_xor_sync(0xFFFFu, S1, o);
            }
            if (lane == 0) {
                float s1 = (float)(((double)S1 + 0.5 * (double)N1) * (1.0 / 65536.0));
                float s0 = (float)Stot - s1;
                unsigned N0 = (unsigned)NPIX - N1;
                float c1 = s1 / (float)max(N1, 1u);
                float c0 = s0 / (float)max(N0, 1u);
                float t  = 0.5f * (c0 + c1);
                int qn = (int)floorf(t * 65536.0f - 0.5f);
                if (qn == qt) {                      // fixed point: further steps no-op
                    sc->qt = qn; sc->done = 1;
                } else if (qn == prev) {             // 2-cycle: pick by parity
                    int m = 19 - it;
                    sc->qt = ((m & 1) == 0) ? qn : qt;
                    sc->done = 1;
                } else {
                    prev = qt;
                    sc->qt = qn;
                }
            }
        }
        __syncthreads();
        qt = sc->qt;
        if (sc->done) break;
    }

    // ---------------- Phase 3a: border vote ----------------
    if (tid < 4) sc->border[tid] = 0;
    __syncthreads();
    #pragma unroll
    for (int i = tid; i < 1024; i += NT) {
        const int g = i >> 8;          // 0:row0 1:row255 2:col0 3:col255 (warp-uniform)
        const int j = i & 255;
        int qv;
        if      (g == 0) qv = (int)qs[j];
        else if (g == 1) qv = (int)qs[65280 + j];
        else if (g == 2) qv = (int)qs[j << 8];
        else             qv = (int)qs[(j << 8) + 255];
        unsigned c = (qv > qt) ? 1u : 0u;
        #pragma unroll
        for (int o = 16; o; o >>= 1) c += __shfl_xor_sync(~0u, c, o);
        if (lane == 0) atomicAdd(&sc->border[g], c);
    }
    __syncthreads();
    if (tid == 0) {
        int num = (sc->border[0] > 128u) + (sc->border[1] > 128u)
                + (sc->border[2] > 128u) + (sc->border[3] > 128u);
        sc->flip = (num >= 3) ? 1 : 0;
    }
    __syncthreads();
    const int flip = sc->flip;

    // ---------------- Phase 3b: loss vs sr_mask (TMA-staged) ----------------
    float acc = 0.0f;
    for (int k = 0; k < NCH3; k++) {
        const int s = k & 1;
        const unsigned par = (unsigned)((k >> 1) & 1);
        mbar_wait(fb[s], par);

        const float4* sp = (const float4*)(stg + s * CH3);
        // thread handles 16 px: float4 indices tid*4..tid*4+3; q128 idx k*1024 + tid*2 (+1)
        #pragma unroll
        for (int g = 0; g < 2; g++) {
            uint4 v = q128[k * (CH3/8) + tid * 2 + g];
            float4 s0 = sp[tid * 4 + g * 2 + 0];
            float4 s1 = sp[tid * 4 + g * 2 + 1];
            int m0 = (((int)(v.x & 0xFFFFu)) > qt) ^ flip;
            int m1 = (((int)(v.x >> 16))     > qt) ^ flip;
            int m2 = (((int)(v.y & 0xFFFFu)) > qt) ^ flip;
            int m3 = (((int)(v.y >> 16))     > qt) ^ flip;
            int m4 = (((int)(v.z & 0xFFFFu)) > qt) ^ flip;
            int m5 = (((int)(v.z >> 16))     > qt) ^ flip;
            int m6 = (((int)(v.w & 0xFFFFu)) > qt) ^ flip;
            int m7 = (((int)(v.w >> 16))     > qt) ^ flip;
            float d0 = s0.x - (float)m0, d1 = s0.y - (float)m1;
            float d2 = s0.z - (float)m2, d3 = s0.w - (float)m3;
            float d4 = s1.x - (float)m4, d5 = s1.y - (float)m5;
            float d6 = s1.z - (float)m6, d7 = s1.w - (float)m7;
            acc += d0*d0 + d1*d1 + d2*d2 + d3*d3;
            acc += d4*d4 + d5*d5 + d6*d6 + d7*d7;
        }

        mbar_arrive(eb[s]);
        if (tid == 0 && k + 2 < NCH3) {
            mbar_wait(eb[s], par);
            mbar_expect_tx(fb[s], CH3 * 4);
            bulk_g2s(stg_u32 + (unsigned)(s * CH3 * 4), srb + (k + 2) * CH3, CH3 * 4, fb[s]);
        }
    }

    #pragma unroll
    for (int o = 16; o; o >>= 1) acc += __shfl_xor_sync(~0u, acc, o);
    if (lane == 0) sc->facc[warp] = acc;
    __syncthreads();

    // ---------------- Phase 4: per-CTA partial + last-CTA finalize ----------------
    if (warp == 0) {
        float a = (lane < 16) ? sc->facc[lane] : 0.0f;
        #pragma unroll
        for (int o = 8; o; o >>= 1) a += __shfl_xor_sync(~0u, a, o);
        a = __shfl_sync(~0u, a, 0);
        if (lane == 0) g_partials[b] = (double)a;

        unsigned old = 0;
        if (lane == 0) {
            __threadfence();
            old = atomicAdd(&g_count, 1u);
        }
        old = __shfl_sync(~0u, old, 0);

        if (old == (unsigned)(B - 1)) {          // last CTA: finalize
            __threadfence();
            volatile double* vp = g_partials;
            double t = 0.0;
            for (int i = lane; i < B; i += 32) t += vp[i];
            #pragma unroll
            for (int o = 16; o; o >>= 1) t += __shfl_xor_sync(~0u, t, o);
            if (lane == 0) {
                out[0] = (float)(t / ((double)B * (double)NPIX));
                g_count = 0;                     // reset for next graph replay
            }
        }
    }
}

extern "C" void kernel_launch(void* const* d_in, const int* in_sizes, int n_in,
                              void* d_out, int out_size)
{
    const float* hr = (const float*)d_in[0];
    const float* sr = (const float*)d_in[1];
    int B = in_sizes[1] / NPIX;

    cudaFuncSetAttribute(mask_loss_main,
                         cudaFuncAttributeMaxDynamicSharedMemorySize, SMEM_TOTAL);

    mask_loss_main<<<B, NT, SMEM_TOTAL>>>(hr, sr, (float*)d_out, B);
}

// round 6
// speedup vs baseline: 1.0328x; 1.0328x over previous
#include <cuda_runtime.h>

#define NPIX  65536   // 256*256
#define NT    1024
#define KS    8       // NPIX/8/NT uint4 (8 x u16) groups per thread for Lloyd scan
#define KP1   8       // phase-1 outer steps (2 float4-groups each)
#define KP3   8       // phase-3 outer steps (2 float4-groups each)

#define Q_BYTES     131072
#define SCR_OFF     131072
#define STAGE_OFF   132096            // 131072 + 1024 (16B aligned)
#define STAGE_PX    16384             // first quarter of sr, 64KB
#define SMEM_TOTAL  (STAGE_OFF + STAGE_PX * 4)

__device__ double   g_partials[1024];
__device__ unsigned g_count = 0;

struct Scratch {
    unsigned long long mbar;
    unsigned nred[32];
    unsigned sred[32];
    float    fmin[32], fmax[32], facc[32];
    int      qt, done, flip;
    unsigned border[4];
};

__device__ __forceinline__ unsigned smem_u32(const void* p) {
    unsigned r;
    asm("{ .reg .u64 t; cvta.to.shared.u64 t, %1; cvt.u32.u64 %0, t; }"
        : "=r"(r) : "l"(p));
    return r;
}
__device__ __forceinline__ void mbar_init(unsigned mbar, unsigned count) {
    asm volatile("mbarrier.init.shared.b64 [%0], %1;" :: "r"(mbar), "r"(count) : "memory");
}
__device__ __forceinline__ void mbar_expect_tx(unsigned mbar, unsigned bytes) {
    asm volatile("mbarrier.arrive.expect_tx.shared.b64 _, [%0], %1;"
                 :: "r"(mbar), "r"(bytes) : "memory");
}
__device__ __forceinline__ void mbar_wait(unsigned mbar, unsigned parity) {
    asm volatile(
        "{\n\t.reg .pred P;\n\t"
        "WL_%=:\n\t"
        "mbarrier.try_wait.parity.acquire.cta.shared::cta.b64 P, [%0], %1, 0x989680;\n\t"
        "@P bra WD_%=;\n\t"
        "bra WL_%=;\n\t"
        "WD_%=:\n\t}"
        :: "r"(mbar), "r"(parity) : "memory");
}
__device__ __forceinline__ void bulk_g2s(unsigned dst_smem, const void* src, unsigned bytes,
                                         unsigned mbar) {
    asm volatile(
        "cp.async.bulk.shared::cluster.global.mbarrier::complete_tx::bytes [%0], [%1], %2, [%3];"
        :: "r"(dst_smem), "l"(src), "r"(bytes), "r"(mbar) : "memory");
}

extern "C" __global__ void __launch_bounds__(NT, 1)
mask_loss_main(const float* __restrict__ hr, const float* __restrict__ sr,
               float* __restrict__ out, int B)
{
    extern __shared__ unsigned char smem[];
    unsigned short* qs   = (unsigned short*)smem;
    uint4*          q128 = (uint4*)smem;
    float*          stg  = (float*)(smem + STAGE_OFF);
    Scratch* sc = (Scratch*)(smem + SCR_OFF);

    const int tid  = threadIdx.x;
    const int lane = tid & 31;
    const int warp = tid >> 5;
    const int b    = blockIdx.x;

    const unsigned mb = smem_u32(&sc->mbar);
    if (tid == 0) mbar_init(mb, 1);
    __syncthreads();

    // sr prefetch (first quarter) — no dependencies, overlaps phases 1+2
    const float* srb = sr + (size_t)b * NPIX;
    if (tid == 0) {
        mbar_expect_tx(mb, STAGE_PX * 4);
        bulk_g2s(smem_u32(stg), srb, STAGE_PX * 4, mb);
    }

    // ---------------- Phase 1: gray + quantize into SMEM, min/max/sum ----------------
    const float4* p0 = (const float4*)(hr + (size_t)b * 3 * NPIX);
    const float4* p1 = p0 + NPIX / 4;
    const float4* p2 = p1 + NPIX / 4;

    float gmin = 3.0e38f, gmax = -3.0e38f;
    unsigned sq = 0;                 // <= 64 px * 65535 = 4.19e6, fits u32
    const float inv3 = 1.0f / 3.0f;

    #pragma unroll
    for (int k = 0; k < KP1; k++) {
        const int g0 = k * 2048 + 2 * tid;   // two adjacent float4 groups
        float4 a0 = p0[g0],     c0 = p1[g0],     d0 = p2[g0];
        float4 a1 = p0[g0 + 1], c1 = p1[g0 + 1], d1 = p2[g0 + 1];

        float x0 = (a0.x + c0.x + d0.x) * inv3;
        float x1 = (a0.y + c0.y + d0.y) * inv3;
        float x2 = (a0.z + c0.z + d0.z) * inv3;
        float x3 = (a0.w + c0.w + d0.w) * inv3;
        float x4 = (a1.x + c1.x + d1.x) * inv3;
        float x5 = (a1.y + c1.y + d1.y) * inv3;
        float x6 = (a1.z + c1.z + d1.z) * inv3;
        float x7 = (a1.w + c1.w + d1.w) * inv3;

        gmin = fminf(gmin, fminf(fminf(fminf(x0, x1), fminf(x2, x3)),
                                 fminf(fminf(x4, x5), fminf(x6, x7))));
        gmax = fmaxf(gmax, fmaxf(fmaxf(fmaxf(x0, x1), fmaxf(x2, x3)),
                                 fmaxf(fmaxf(x4, x5), fmaxf(x6, x7))));

        unsigned q0 = (unsigned)fminf(x0 * 65536.0f, 65535.0f);
        unsigned q1 = (unsigned)fminf(x1 * 65536.0f, 65535.0f);
        unsigned q2 = (unsigned)fminf(x2 * 65536.0f, 65535.0f);
        unsigned q3 = (unsigned)fminf(x3 * 65536.0f, 65535.0f);
        unsigned q4 = (unsigned)fminf(x4 * 65536.0f, 65535.0f);
        unsigned q5 = (unsigned)fminf(x5 * 65536.0f, 65535.0f);
        unsigned q6 = (unsigned)fminf(x6 * 65536.0f, 65535.0f);
        unsigned q7 = (unsigned)fminf(x7 * 65536.0f, 65535.0f);
        sq += q0 + q1 + q2 + q3 + q4 + q5 + q6 + q7;

        uint4 pk;
        pk.x = q0 | (q1 << 16);
        pk.y = q2 | (q3 << 16);
        pk.z = q4 | (q5 << 16);
        pk.w = q6 | (q7 << 16);
        q128[k * 1024 + tid] = pk;
    }

    #pragma unroll
    for (int o = 16; o; o >>= 1) {
        gmin = fminf(gmin, __shfl_xor_sync(~0u, gmin, o));
        gmax = fmaxf(gmax, __shfl_xor_sync(~0u, gmax, o));
        sq  += __shfl_xor_sync(~0u, sq, o);
    }
    if (lane == 0) { sc->fmin[warp] = gmin; sc->fmax[warp] = gmax; sc->nred[warp] = sq; }
    __syncthreads();

    double Stot = 0.0;   // valid only in (warp 0, lane 0)
    if (warp == 0) {
        float mn = sc->fmin[lane];
        float mx = sc->fmax[lane];
        unsigned long long s = (unsigned long long)sc->nred[lane];
        #pragma unroll
        for (int o = 16; o; o >>= 1) {
            mn = fminf(mn, __shfl_xor_sync(~0u, mn, o));
            mx = fmaxf(mx, __shfl_xor_sync(~0u, mx, o));
            s += __shfl_xor_sync(~0u, s, o);
        }
        if (lane == 0) {
            Stot = ((double)s + 32768.0) * (1.0 / 65536.0);
            float t = 0.5f * (mn + mx);                 // init c0=min, c1=max
            sc->qt   = (int)floorf(t * 65536.0f - 0.5f);
            sc->done = 0;
        }
    }
    __syncthreads();

    // ---------------- Phase 2: Lloyd iterations (integer threshold map) ----------------
    int qt = sc->qt;
    int prev = -0x70000000;  // thread-0-only history (tau_{i-1})

    for (int it = 0; it < 20; it++) {
        unsigned n = 0, s = 0;
        #pragma unroll
        for (int k = 0; k < KS; k++) {
            uint4 v = q128[tid + k * NT];
            int a0 = (int)(v.x & 0xFFFFu), a1 = (int)(v.x >> 16);
            int a2 = (int)(v.y & 0xFFFFu), a3 = (int)(v.y >> 16);
            int a4 = (int)(v.z & 0xFFFFu), a5 = (int)(v.z >> 16);
            int a6 = (int)(v.w & 0xFFFFu), a7 = (int)(v.w >> 16);
            if (a0 > qt) { n++; s += (unsigned)a0; }
            if (a1 > qt) { n++; s += (unsigned)a1; }
            if (a2 > qt) { n++; s += (unsigned)a2; }
            if (a3 > qt) { n++; s += (unsigned)a3; }
            if (a4 > qt) { n++; s += (unsigned)a4; }
            if (a5 > qt) { n++; s += (unsigned)a5; }
            if (a6 > qt) { n++; s += (unsigned)a6; }
            if (a7 > qt) { n++; s += (unsigned)a7; }
        }
        #pragma unroll
        for (int o = 16; o; o >>= 1) {
            n += __shfl_xor_sync(~0u, n, o);
            s += __shfl_xor_sync(~0u, s, o);
        }
        if (lane == 0) { sc->nred[warp] = n; sc->sred[warp] = s; }
        __syncthreads();

        if (warp == 0) {
            unsigned N1 = sc->nred[lane];
            unsigned long long S1 = (unsigned long long)sc->sred[lane];
            #pragma unroll
            for (int o = 16; o; o >>= 1) {
                N1 += __shfl_xor_sync(~0u, N1, o);
                S1 += __shfl_xor_sync(~0u, S1, o);
            }
            if (lane == 0) {
                float s1 = (float)(((double)S1 + 0.5 * (double)N1) * (1.0 / 65536.0));
                float s0 = (float)Stot - s1;
                unsigned N0 = (unsigned)NPIX - N1;
                float c1 = s1 / (float)max(N1, 1u);
                float c0 = s0 / (float)max(N0, 1u);
                float t  = 0.5f * (c0 + c1);
                int qn = (int)floorf(t * 65536.0f - 0.5f);
                if (qn == qt) {                      // fixed point: further steps no-op
                    sc->qt = qn; sc->done = 1;
                } else if (qn == prev) {             // 2-cycle: pick by parity
                    int m = 19 - it;
                    sc->qt = ((m & 1) == 0) ? qn : qt;
                    sc->done = 1;
                } else {
                    prev = qt;
                    sc->qt = qn;
                }
            }
        }
        __syncthreads();
        qt = sc->qt;
        if (sc->done) break;
    }

    // ---------------- Phase 3a: border vote ----------------
    if (tid < 4) sc->border[tid] = 0;
    __syncthreads();
    {
        const int g = tid >> 8;          // 0:row0 1:row255 2:col0 3:col255 (warp-uniform)
        const int j = tid & 255;
        int qv;
        if      (g == 0) qv = (int)qs[j];
        else if (g == 1) qv = (int)qs[65280 + j];
        else if (g == 2) qv = (int)qs[j << 8];
        else             qv = (int)qs[(j << 8) + 255];
        unsigned c = (qv > qt) ? 1u : 0u;
        #pragma unroll
        for (int o = 16; o; o >>= 1) c += __shfl_xor_sync(~0u, c, o);
        if (lane == 0) atomicAdd(&sc->border[g], c);
    }
    __syncthreads();
    if (tid == 0) {
        int num = (sc->border[0] > 128u) + (sc->border[1] > 128u)
                + (sc->border[2] > 128u) + (sc->border[3] > 128u);
        sc->flip = (num >= 3) ? 1 : 0;
    }
    __syncthreads();
    const int flip = sc->flip;

    // ---------------- Phase 3b: loss vs sr_mask (first quarter from SMEM stage) ----------------
    mbar_wait(mb, 0);                        // sr prefetch complete (long since done)
    const float4* spg = (const float4*)srb;
    const float4* sps = (const float4*)stg;

    float acc = 0.0f;
    #pragma unroll
    for (int k = 0; k < KP3; k++) {
        const int g0 = k * 2048 + 2 * tid;   // float4 index (matches q128[k*1024+tid])
        uint4 v = q128[k * 1024 + tid];
        float4 s0, s1;
        if (k < 2) { s0 = sps[g0]; s1 = sps[g0 + 1]; }
        else       { s0 = spg[g0]; s1 = spg[g0 + 1]; }

        int m0 = (((int)(v.x & 0xFFFFu)) > qt) ^ flip;
        int m1 = (((int)(v.x >> 16))     > qt) ^ flip;
        int m2 = (((int)(v.y & 0xFFFFu)) > qt) ^ flip;
        int m3 = (((int)(v.y >> 16))     > qt) ^ flip;
        int m4 = (((int)(v.z & 0xFFFFu)) > qt) ^ flip;
        int m5 = (((int)(v.z >> 16))     > qt) ^ flip;
        int m6 = (((int)(v.w & 0xFFFFu)) > qt) ^ flip;
        int m7 = (((int)(v.w >> 16))     > qt) ^ flip;

        float d0 = s0.x - (float)m0, d1 = s0.y - (float)m1;
        float d2 = s0.z - (float)m2, d3 = s0.w - (float)m3;
        float d4 = s1.x - (float)m4, d5 = s1.y - (float)m5;
        float d6 = s1.z - (float)m6, d7 = s1.w - (float)m7;
        acc += d0*d0 + d1*d1 + d2*d2 + d3*d3;
        acc += d4*d4 + d5*d5 + d6*d6 + d7*d7;
    }

    #pragma unroll
    for (int o = 16; o; o >>= 1) acc += __shfl_xor_sync(~0u, acc, o);
    if (lane == 0) sc->facc[warp] = acc;
    __syncthreads();

    // ---------------- Phase 4: per-CTA partial + last-CTA finalize ----------------
    if (warp == 0) {
        float a = sc->facc[lane];
        #pragma unroll
        for (int o = 16; o; o >>= 1) a += __shfl_xor_sync(~0u, a, o);
        a = __shfl_sync(~0u, a, 0);
        if (lane == 0) g_partials[b] = (double)a;

        unsigned old = 0;
        if (lane == 0) {
            __threadfence();
            old = atomicAdd(&g_count, 1u);
        }
        old = __shfl_sync(~0u, old, 0);

        if (old == (unsigned)(B - 1)) {          // last CTA: finalize
            __threadfence();
            volatile double* vp = g_partials;
            double t = 0.0;
            for (int i = lane; i < B; i += 32) t += vp[i];
            #pragma unroll
            for (int o = 16; o; o >>= 1) t += __shfl_xor_sync(~0u, t, o);
            if (lane == 0) {
                out[0] = (float)(t / ((double)B * (double)NPIX));
                g_count = 0;                     // reset for next graph replay
            }
        }
    }
}

extern "C" void kernel_launch(void* const* d_in, const int* in_sizes, int n_in,
                              void* d_out, int out_size)
{
    const float* hr = (const float*)d_in[0];
    const float* sr = (const float*)d_in[1];
    int B = in_sizes[1] / NPIX;

    cudaFuncSetAttribute(mask_loss_main,
                         cudaFuncAttributeMaxDynamicSharedMemorySize, SMEM_TOTAL);

    mask_loss_main<<<B, NT, SMEM_TOTAL>>>(hr, sr, (float*)d_out, B);
}

// round 7
// speedup vs baseline: 1.6770x; 1.6237x over previous
#include <cuda_runtime.h>
#include <cuda_fp16.h>

#define NPIX  65536   // 256*256
#define NT    1024
#define KS    8       // NPIX/8/NT uint4 (8 x f16 px) groups per thread for Lloyd scan
#define KP1   8       // phase-1 outer steps (2 float4-groups each)
#define KP3   8       // phase-3 outer steps

#define SCR_OFF     131072
#define STAGE_OFF   132096            // 131072 + 1024 (16B aligned)
#define STAGE_PX    16384             // first quarter of sr, 64KB
#define SMEM_TOTAL  (STAGE_OFF + STAGE_PX * 4)

__device__ double   g_partials[1024];
__device__ unsigned g_count = 0;

struct Scratch {
    unsigned long long mbar;
    float    nred[32];
    float    sred[32];
    float    fmin[32], fmax[32], facc[32];
    int      hq[24];                  // threshold-bits history (iter 0..20)
    int      qt, done, flip;
    unsigned border[4];
};

__device__ __forceinline__ unsigned smem_u32(const void* p) {
    unsigned r;
    asm("{ .reg .u64 t; cvta.to.shared.u64 t, %1; cvt.u32.u64 %0, t; }"
        : "=r"(r) : "l"(p));
    return r;
}
__device__ __forceinline__ void mbar_init(unsigned mbar, unsigned count) {
    asm volatile("mbarrier.init.shared.b64 [%0], %1;" :: "r"(mbar), "r"(count) : "memory");
}
__device__ __forceinline__ void mbar_expect_tx(unsigned mbar, unsigned bytes) {
    asm volatile("mbarrier.arrive.expect_tx.shared.b64 _, [%0], %1;"
                 :: "r"(mbar), "r"(bytes) : "memory");
}
__device__ __forceinline__ void mbar_wait(unsigned mbar, unsigned parity) {
    asm volatile(
        "{\n\t.reg .pred P;\n\t"
        "WL_%=:\n\t"
        "mbarrier.try_wait.parity.acquire.cta.shared::cta.b64 P, [%0], %1, 0x989680;\n\t"
        "@P bra WD_%=;\n\t"
        "bra WL_%=;\n\t"
        "WD_%=:\n\t}"
        :: "r"(mbar), "r"(parity) : "memory");
}
__device__ __forceinline__ void bulk_g2s(unsigned dst_smem, const void* src, unsigned bytes,
                                         unsigned mbar) {
    asm volatile(
        "cp.async.bulk.shared::cluster.global.mbarrier::complete_tx::bytes [%0], [%1], %2, [%3];"
        :: "r"(dst_smem), "l"(src), "r"(bytes), "r"(mbar) : "memory");
}

extern "C" __global__ void __launch_bounds__(NT, 1)
mask_loss_main(const float* __restrict__ hr, const float* __restrict__ sr,
               float* __restrict__ out, int B)
{
    extern __shared__ unsigned char smem[];
    unsigned short* qs   = (unsigned short*)smem;   // half bits (positive => order = bit order)
    uint4*          q128 = (uint4*)smem;            // 8 px (4 x half2) per uint4
    float*          stg  = (float*)(smem + STAGE_OFF);
    Scratch* sc = (Scratch*)(smem + SCR_OFF);

    const int tid  = threadIdx.x;
    const int lane = tid & 31;
    const int warp = tid >> 5;
    const int b    = blockIdx.x;

    const unsigned mb = smem_u32(&sc->mbar);
    if (tid == 0) mbar_init(mb, 1);
    __syncthreads();

    // sr prefetch (first quarter) — no dependencies, overlaps phases 1+2
    const float* srb = sr + (size_t)b * NPIX;
    if (tid == 0) {
        mbar_expect_tx(mb, STAGE_PX * 4);
        bulk_g2s(smem_u32(stg), srb, STAGE_PX * 4, mb);
    }

    // ---------------- Phase 1: gray -> half2 into SMEM, min/max/sum ----------------
    const float4* p0 = (const float4*)(hr + (size_t)b * 3 * NPIX);
    const float4* p1 = p0 + NPIX / 4;
    const float4* p2 = p1 + NPIX / 4;

    float gmin = 3.0e38f, gmax = -3.0e38f;
    float ssum = 0.0f;
    const float inv3 = 1.0f / 3.0f;

    #pragma unroll
    for (int k = 0; k < KP1; k++) {
        const int g0 = k * 2048 + 2 * tid;   // two adjacent float4 groups
        float4 a0 = p0[g0],     c0 = p1[g0],     d0 = p2[g0];
        float4 a1 = p0[g0 + 1], c1 = p1[g0 + 1], d1 = p2[g0 + 1];

        float x0 = (a0.x + c0.x + d0.x) * inv3;
        float x1 = (a0.y + c0.y + d0.y) * inv3;
        float x2 = (a0.z + c0.z + d0.z) * inv3;
        float x3 = (a0.w + c0.w + d0.w) * inv3;
        float x4 = (a1.x + c1.x + d1.x) * inv3;
        float x5 = (a1.y + c1.y + d1.y) * inv3;
        float x6 = (a1.z + c1.z + d1.z) * inv3;
        float x7 = (a1.w + c1.w + d1.w) * inv3;

        gmin = fminf(gmin, fminf(fminf(fminf(x0, x1), fminf(x2, x3)),
                                 fminf(fminf(x4, x5), fminf(x6, x7))));
        gmax = fmaxf(gmax, fmaxf(fmaxf(fmaxf(x0, x1), fmaxf(x2, x3)),
                                 fmaxf(fmaxf(x4, x5), fmaxf(x6, x7))));
        ssum += ((x0 + x1) + (x2 + x3)) + ((x4 + x5) + (x6 + x7));

        __half2 h0 = __floats2half2_rn(x0, x1);
        __half2 h1 = __floats2half2_rn(x2, x3);
        __half2 h2 = __floats2half2_rn(x4, x5);
        __half2 h3 = __floats2half2_rn(x6, x7);
        uint4 pk;
        pk.x = *(unsigned*)&h0;
        pk.y = *(unsigned*)&h1;
        pk.z = *(unsigned*)&h2;
        pk.w = *(unsigned*)&h3;
        q128[k * 1024 + tid] = pk;
    }

    #pragma unroll
    for (int o = 16; o; o >>= 1) {
        gmin = fminf(gmin, __shfl_xor_sync(~0u, gmin, o));
        gmax = fmaxf(gmax, __shfl_xor_sync(~0u, gmax, o));
        ssum += __shfl_xor_sync(~0u, ssum, o);
    }
    if (lane == 0) { sc->fmin[warp] = gmin; sc->fmax[warp] = gmax; sc->sred[warp] = ssum; }
    __syncthreads();

    float Stot = 0.0f;   // valid only in (warp 0, lane 0)
    if (warp == 0) {
        float mn = sc->fmin[lane];
        float mx = sc->fmax[lane];
        float s  = sc->sred[lane];
        #pragma unroll
        for (int o = 16; o; o >>= 1) {
            mn = fminf(mn, __shfl_xor_sync(~0u, mn, o));
            mx = fmaxf(mx, __shfl_xor_sync(~0u, mx, o));
            s += __shfl_xor_sync(~0u, s, o);
        }
        if (lane == 0) {
            Stot = s;
            float t = 0.5f * (mn + mx);                 // init c0=min, c1=max
            int qb = (int)__half_as_ushort(__float2half_rn(t));
            sc->qt = qb;
            sc->hq[0] = qb;
            sc->done = 0;
        }
    }
    __syncthreads();

    // ---------------- Phase 2: Lloyd iterations (f16x2 scan + full-history exit) ----------------
    int qt = sc->qt;

    for (int it = 0; it < 20; it++) {
        const __half2 t2 = __half2half2(__ushort_as_half((unsigned short)qt));
        __half2 n2 = __floats2half2_rn(0.0f, 0.0f);
        __half2 s2 = n2;

        #pragma unroll
        for (int k = 0; k < KS; k++) {
            uint4 v = q128[tid + k * NT];
            __half2 a0 = *(__half2*)&v.x;
            __half2 a1 = *(__half2*)&v.y;
            __half2 a2 = *(__half2*)&v.z;
            __half2 a3 = *(__half2*)&v.w;
            __half2 m0 = __hgt2(a0, t2);
            __half2 m1 = __hgt2(a1, t2);
            __half2 m2 = __hgt2(a2, t2);
            __half2 m3 = __hgt2(a3, t2);
            n2 = __hadd2(n2, __hadd2(__hadd2(m0, m1), __hadd2(m2, m3)));
            s2 = __hfma2(m0, a0, s2);
            s2 = __hfma2(m1, a1, s2);
            s2 = __hfma2(m2, a2, s2);
            s2 = __hfma2(m3, a3, s2);
        }

        float n = __low2float(n2) + __high2float(n2);   // counts <= 32/half: exact
        float s = __low2float(s2) + __high2float(s2);
        #pragma unroll
        for (int o = 16; o; o >>= 1) {
            n += __shfl_xor_sync(~0u, n, o);
            s += __shfl_xor_sync(~0u, s, o);
        }
        if (lane == 0) { sc->nred[warp] = n; sc->sred[warp] = s; }
        __syncthreads();

        if (warp == 0) {
            float N1f = sc->nred[lane];
            float S1  = sc->sred[lane];
            #pragma unroll
            for (int o = 16; o; o >>= 1) {
                N1f += __shfl_xor_sync(~0u, N1f, o);
                S1  += __shfl_xor_sync(~0u, S1, o);
            }
            if (lane == 0) {
                int N1 = (int)rintf(N1f);
                int N0 = NPIX - N1;
                float s0 = Stot - S1;
                float c1 = S1 / (float)max(N1, 1);
                float c0 = s0 / (float)max(N0, 1);
                float t  = 0.5f * (c0 + c1);
                int qb = (int)__half_as_ushort(__float2half_rn(t));

                int fin = -1;
                #pragma unroll
                for (int j = 0; j < 21; j++) {
                    if (j <= it && fin < 0 && sc->hq[j] == qb) {
                        int L   = it + 1 - j;          // cycle length
                        int idx = j + ((20 - j) % L);  // index of qt_20 within cycle
                        fin = sc->hq[idx];
                    }
                }
                if (fin >= 0) { sc->qt = fin; sc->done = 1; }
                else          { sc->hq[it + 1] = qb; sc->qt = qb; }
            }
        }
        __syncthreads();
        qt = sc->qt;
        if (sc->done) break;
    }

    // ---------------- Phase 3a: border vote (bit compare on positive halves) ----------------
    if (tid < 4) sc->border[tid] = 0;
    __syncthreads();
    {
        const int g = tid >> 8;          // 0:row0 1:row255 2:col0 3:col255 (warp-uniform)
        const int j = tid & 255;
        int qv;
        if      (g == 0) qv = (int)qs[j];
        else if (g == 1) qv = (int)qs[65280 + j];
        else if (g == 2) qv = (int)qs[j << 8];
        else             qv = (int)qs[(j << 8) + 255];
        unsigned c = (qv > qt) ? 1u : 0u;
        #pragma unroll
        for (int o = 16; o; o >>= 1) c += __shfl_xor_sync(~0u, c, o);
        if (lane == 0) atomicAdd(&sc->border[g], c);
    }
    __syncthreads();
    if (tid == 0) {
        int num = (sc->border[0] > 128u) + (sc->border[1] > 128u)
                + (sc->border[2] > 128u) + (sc->border[3] > 128u);
        sc->flip = (num >= 3) ? 1 : 0;
    }
    __syncthreads();
    const int flip = sc->flip;

    // ---------------- Phase 3b: loss vs sr_mask (first quarter from SMEM stage) ----------------
    mbar_wait(mb, 0);
    const float4* spg = (const float4*)srb;
    const float4* sps = (const float4*)stg;
    const __half2 t2  = __half2half2(__ushort_as_half((unsigned short)qt));
    const float fofs  = flip ? 1.0f : 0.0f;       // mask_used = fofs + fsgn * m
    const float fsgn  = flip ? -1.0f : 1.0f;

    float acc = 0.0f;
    #pragma unroll
    for (int k = 0; k < KP3; k++) {
        const int g0 = k * 2048 + 2 * tid;
        uint4 v = q128[k * 1024 + tid];
        float4 s0, s1;
        if (k < 2) { s0 = sps[g0]; s1 = sps[g0 + 1]; }
        else       { s0 = spg[g0]; s1 = spg[g0 + 1]; }

        __half2 a0 = *(__half2*)&v.x;
        __half2 a1 = *(__half2*)&v.y;
        __half2 a2 = *(__half2*)&v.z;
        __half2 a3 = *(__half2*)&v.w;
        float2 m0 = __half22float2(__hgt2(a0, t2));
        float2 m1 = __half22float2(__hgt2(a1, t2));
        float2 m2 = __half22float2(__hgt2(a2, t2));
        float2 m3 = __half22float2(__hgt2(a3, t2));

        float d0 = s0.x - fmaf(fsgn, m0.x, fofs);
        float d1 = s0.y - fmaf(fsgn, m0.y, fofs);
        float d2 = s0.z - fmaf(fsgn, m1.x, fofs);
        float d3 = s0.w - fmaf(fsgn, m1.y, fofs);
        float d4 = s1.x - fmaf(fsgn, m2.x, fofs);
        float d5 = s1.y - fmaf(fsgn, m2.y, fofs);
        float d6 = s1.z - fmaf(fsgn, m3.x, fofs);
        float d7 = s1.w - fmaf(fsgn, m3.y, fofs);
        acc += d0*d0 + d1*d1 + d2*d2 + d3*d3;
        acc += d4*d4 + d5*d5 + d6*d6 + d7*d7;
    }

    #pragma unroll
    for (int o = 16; o; o >>= 1) acc += __shfl_xor_sync(~0u, acc, o);
    if (lane == 0) sc->facc[warp] = acc;
    __syncthreads();

    // ---------------- Phase 4: per-CTA partial + last-CTA finalize ----------------
    if (warp == 0) {
        float a = sc->facc[lane];
        #pragma unroll
        for (int o = 16; o; o >>= 1) a += __shfl_xor_sync(~0u, a, o);
        a = __shfl_sync(~0u, a, 0);
        if (lane == 0) g_partials[b] = (double)a;

        unsigned old = 0;
        if (lane == 0) {
            __threadfence();
            old = atomicAdd(&g_count, 1u);
        }
        old = __shfl_sync(~0u, old, 0);

        if (old == (unsigned)(B - 1)) {          // last CTA: finalize
            __threadfence();
            volatile double* vp = g_partials;
            double t = 0.0;
            for (int i = lane; i < B; i += 32) t += vp[i];
            #pragma unroll
            for (int o = 16; o; o >>= 1) t += __shfl_xor_sync(~0u, t, o);
            if (lane == 0) {
                out[0] = (float)(t / ((double)B * (double)NPIX));
                g_count = 0;                     // reset for next graph replay
            }
        }
    }
}

extern "C" void kernel_launch(void* const* d_in, const int* in_sizes, int n_in,
                              void* d_out, int out_size)
{
    const float* hr = (const float*)d_in[0];
    const float* sr = (const float*)d_in[1];
    int B = in_sizes[1] / NPIX;

    cudaFuncSetAttribute(mask_loss_main,
                         cudaFuncAttributeMaxDynamicSharedMemorySize, SMEM_TOTAL);

    mask_loss_main<<<B, NT, SMEM_TOTAL>>>(hr, sr, (float*)d_out, B);
}